// round 7
// baseline (speedup 1.0000x reference)
#include <cuda_runtime.h>
#include <cuda_fp16.h>
#include <cstdint>

#define BATCH 8
#define CH    128
#define HH    48
#define WW    64
#define NN    (HH*WW)   // 3072

#define S2F ((float)(1.4426950408889634 * 0.088388347648318447))

__device__ __half g_f0h[BATCH*NN*CH];
__device__ __half g_f1h[BATCH*NN*CH];
__device__ __half g_qh [BATCH*NN*CH];
__device__ __half g_kh [BATCH*NN*CH];

__device__ __forceinline__ uint32_t smem_u32(const void* p) {
    uint32_t a;
    asm("{ .reg .u64 t; cvta.to.shared.u64 t, %1; cvt.u32.u64 %0, t; }" : "=r"(a) : "l"(p));
    return a;
}
__device__ __forceinline__ void ldsm4(uint32_t* r, uint32_t addr) {
    asm volatile("ldmatrix.sync.aligned.m8n8.x4.shared.b16 {%0,%1,%2,%3}, [%4];"
        : "=r"(r[0]), "=r"(r[1]), "=r"(r[2]), "=r"(r[3]) : "r"(addr));
}
__device__ __forceinline__ void mma16816(float* c, const uint32_t* a, const uint32_t* b) {
    asm volatile("mma.sync.aligned.m16n8k16.row.col.f32.f16.f16.f32 "
        "{%0,%1,%2,%3}, {%4,%5,%6,%7}, {%8,%9}, {%0,%1,%2,%3};"
        : "+f"(c[0]), "+f"(c[1]), "+f"(c[2]), "+f"(c[3])
        : "r"(a[0]), "r"(a[1]), "r"(a[2]), "r"(a[3]), "r"(b[0]), "r"(b[1]));
}
__device__ __forceinline__ float ex2f(float x) {
    float y; asm("ex2.approx.f32 %0, %1;" : "=f"(y) : "f"(x)); return y;
}
#define CP16(dst, src) asm volatile("cp.async.cg.shared.global [%0], [%1], 16;" :: "r"(dst), "l"(src))
#define CP_COMMIT()    asm volatile("cp.async.commit_group;" ::: "memory")
#define CP_WAIT0()     asm volatile("cp.async.wait_group 0;" ::: "memory")

#define RS 136

// Flash smem map: 64-query A tile, double-buffered 64-key B tiles -> 54KB, occ 3
#define FSM_A    0          // 64*RS*2 = 17408
#define FSM_B0   17408      // 17408
#define FSM_B1   34816
#define FSM_V0   52224      // 512 B (64 x + 64 y floats)
#define FSM_V1   52736
#define FSM_RED  53248      // 192 floats
#define FSM_TOT  54016

// Proj smem map (64-row tile; q staged through smem for GEMM2)
#define PSM_F    0          // 17408  (f0 tile)
#define PSM_Q    17408      // 17408  (q tile, fp16)
#define PSM_W    34816      // 34816  (weights fp16, 128x128)
#define PSM_QB   69632      // 512
#define PSM_KB   70144      // 512
#define PSM_TOT  70656

// 64-row fp16 tile prefetch (RS stride)
__device__ __forceinline__ void prefetch_tile64(uint32_t dstBase, const __half* src, int t) {
    #pragma unroll
    for (int it = 0; it < 4; it++) {
        int idx = it * 256 + t;
        int r = idx >> 4, g = idx & 15;
        CP16(dstBase + (uint32_t)((r * RS + g * 8) * 2), src + (size_t)r * CH + g * 8);
    }
}

// ---------------------------------------------------------------------------
// Flash body: 64-query tile, 48 key tiles of 64 keys, cp.async double buffer.
// Warp tile: 16 queries (wr=wid>>1) x 32 keys (wc=wid&1 half); wc pair merged
// through smem at the end. Scores pre-scaled -> p = ex2(score).
// MODE 0: key tile == one grid row y=tile: vx = local idx, vy = tile.
// MODE 1: V = vsrc fp32 [B][2][N].
// ---------------------------------------------------------------------------
template<int MODE>
__device__ __forceinline__ void flash_body(
    const __half* __restrict__ A, const __half* __restrict__ Bm,
    const float* __restrict__ vsrc, float* __restrict__ out,
    int b, int n0, char* smem)
{
    const uint32_t sb = smem_u32(smem);
    const int t = threadIdx.x, wid = t >> 5, lane = t & 31;
    const int wr = wid >> 1, wc = wid & 1;
    const size_t vbase = (size_t)b * 2 * NN;

    {   // query tile: 64 rows
        __half* sA = (__half*)smem;
        const __half* src = A + ((size_t)b * NN + n0) * CH;
        #pragma unroll
        for (int it = 0; it < 4; it++) {
            int idx = it * 256 + t;
            int r = idx >> 4, g = idx & 15;
            *(uint4*)(sA + r * RS + g * 8) = *(const uint4*)(src + (size_t)r * CH + g * 8);
        }
    }

    const __half* Bbase = Bm + (size_t)b * NN * CH;
    prefetch_tile64(sb + FSM_B0, Bbase, t);
    if (MODE == 1 && t < 32) {
        const float* s = (t < 16) ? (vsrc + vbase + t * 4)
                                  : (vsrc + vbase + NN + (t - 16) * 4);
        uint32_t d = sb + FSM_V0 + ((t < 16) ? t * 16 : 256 + (t - 16) * 16);
        CP16(d, s);
    }
    CP_COMMIT();

    const int g8 = (lane >> 3) & 1, g16 = lane >> 4, l7 = lane & 7, tid4 = lane & 3;
    const uint32_t aBase = sb + FSM_A + (uint32_t)(((wr * 16 + l7 + g8 * 8) * RS + g16 * 8) * 2);
    const uint32_t bOff  = (uint32_t)(((wc * 32 + l7 + g16 * 8) * RS + g8 * 8) * 2);

    float L[2] = {0.f, 0.f}, AX[2] = {0.f, 0.f}, AY[2] = {0.f, 0.f};

    for (int tile = 0; tile < NN / 64; tile++) {
        const uint32_t cur = tile & 1;
        CP_WAIT0();
        __syncthreads();

        if (tile + 1 < NN / 64) {
            const int mn = (tile + 1) * 64;
            prefetch_tile64(sb + (cur ? FSM_B0 : FSM_B1), Bbase + (size_t)mn * CH, t);
            if (MODE == 1 && t < 32) {
                const float* s = (t < 16) ? (vsrc + vbase + mn + t * 4)
                                          : (vsrc + vbase + NN + mn + (t - 16) * 4);
                uint32_t d = sb + (cur ? FSM_V0 : FSM_V1)
                           + ((t < 16) ? t * 16 : 256 + (t - 16) * 16);
                CP16(d, s);
            }
            CP_COMMIT();
        }

        const uint32_t bB = sb + (cur ? FSM_B1 : FSM_B0) + bOff;
        const float* sV = (const float*)(smem + (cur ? FSM_V1 : FSM_V0));

        float c[4][4];
        #pragma unroll
        for (int j = 0; j < 4; j++)
            #pragma unroll
            for (int q = 0; q < 4; q++) c[j][q] = 0.f;

        #pragma unroll
        for (int k = 0; k < 8; k++) {
            uint32_t a[4];
            ldsm4(a, aBase + k * 32);
            #pragma unroll
            for (int j2 = 0; j2 < 2; j2++) {
                uint32_t bb[4];
                ldsm4(bb, bB + j2 * (16 * RS * 2) + k * 32);
                mma16816(c[2 * j2],     a, bb);
                mma16816(c[2 * j2 + 1], a, bb + 2);
            }
        }

        float Lt0 = 0.f, Lt1 = 0.f;
        #pragma unroll
        for (int j = 0; j < 4; j++) {
            float p0 = ex2f(c[j][0]);
            float p1 = ex2f(c[j][1]);
            float p2 = ex2f(c[j][2]);
            float p3 = ex2f(c[j][3]);
            if (MODE == 0) {
                float vx0 = (float)(wc * 32 + j * 8 + tid4 * 2);
                float vx1 = vx0 + 1.f;
                Lt0 += p0 + p1;  Lt1 += p2 + p3;
                AX[0] += p0 * vx0 + p1 * vx1;
                AX[1] += p2 * vx0 + p3 * vx1;
            } else {
                int cl = wc * 32 + j * 8 + tid4 * 2;
                float2 x2 = *(const float2*)&sV[cl];
                float2 y2 = *(const float2*)&sV[64 + cl];
                L[0]  += p0 + p1;          L[1]  += p2 + p3;
                AX[0] += p0 * x2.x + p1 * x2.y;
                AX[1] += p2 * x2.x + p3 * x2.y;
                AY[0] += p0 * y2.x + p1 * y2.y;
                AY[1] += p2 * y2.x + p3 * y2.y;
            }
        }
        if (MODE == 0) {
            float vy = (float)tile;   // 64-key tile == one grid row
            L[0] += Lt0;  L[1] += Lt1;
            AY[0] += vy * Lt0;  AY[1] += vy * Lt1;
        }
    }

    #pragma unroll
    for (int o = 1; o <= 2; o <<= 1)
        #pragma unroll
        for (int h = 0; h < 2; h++) {
            L[h]  += __shfl_xor_sync(0xffffffffu, L[h],  o);
            AX[h] += __shfl_xor_sync(0xffffffffu, AX[h], o);
            AY[h] += __shfl_xor_sync(0xffffffffu, AY[h], o);
        }

    float* red = (float*)(smem + FSM_RED);
    if (wc == 1 && tid4 == 0) {
        #pragma unroll
        for (int h = 0; h < 2; h++) {
            int rl = wr * 16 + h * 8 + (lane >> 2);
            red[rl]       = L[h];
            red[64 + rl]  = AX[h];
            red[128 + rl] = AY[h];
        }
    }
    __syncthreads();
    if (wc == 0 && tid4 == 0) {
        float* ob = out + vbase;
        #pragma unroll
        for (int h = 0; h < 2; h++) {
            int rl = wr * 16 + h * 8 + (lane >> 2);
            float Lt  = L[h]  + red[rl];
            float AXt = AX[h] + red[64 + rl];
            float AYt = AY[h] + red[128 + rl];
            int n = n0 + rl;
            float fx = AXt / Lt, fy = AYt / Lt;
            if (MODE == 0) { fx -= (float)(n & (WW - 1)); fy -= (float)(n >> 6); }
            ob[n] = fx;  ob[NN + n] = fy;
        }
    }
}

// ---------------------------------------------------------------------------
// Proj body: 64-row tile.  GEMM1: q = f0 @ qW^T + qb (16q x 64co per warp,
// wc splits co). q -> global + smem. GEMM2: k = (q @ kW^T + kb)*S2 with q
// re-read from smem via ldmatrix. Fits the 85-reg occ-3 cap.
// ---------------------------------------------------------------------------
__device__ __forceinline__ void proj_body(
    const __half* __restrict__ F0, const float* __restrict__ qw,
    const float* __restrict__ qb,  const float* __restrict__ kw,
    const float* __restrict__ kb,
    __half* __restrict__ QH, __half* __restrict__ KH,
    int b, int n0, char* smem)
{
    __half* sF = (__half*)(smem + PSM_F);
    __half* sQ = (__half*)(smem + PSM_Q);
    __half* sW = (__half*)(smem + PSM_W);
    float* qbS = (float*)(smem + PSM_QB);
    float* kbS = (float*)(smem + PSM_KB);
    const uint32_t sbF = smem_u32(sF), sbQ = smem_u32(sQ), sbW = smem_u32(sW);

    const int t = threadIdx.x, wid = t >> 5, lane = t & 31;
    const int wr = wid >> 1, wc = wid & 1;

    {   // f0 tile: 64 rows
        const __half* src = F0 + ((size_t)b * NN + n0) * CH;
        #pragma unroll
        for (int it = 0; it < 4; it++) {
            int idx = it * 256 + t;
            int r = idx >> 4, g = idx & 15;
            *(uint4*)(sF + r * RS + g * 8) = *(const uint4*)(src + (size_t)r * CH + g * 8);
        }
    }
    #pragma unroll
    for (int it = 0; it < 16; it++) {   // qW fp32 -> fp16
        int idx = it * 256 + t;
        int r = idx >> 5, g = idx & 31;
        float4 w = *(const float4*)(qw + (size_t)r * CH + g * 4);
        __half h[4] = {__float2half(w.x), __float2half(w.y), __float2half(w.z), __float2half(w.w)};
        *(uint2*)(sW + r * RS + g * 4) = *(uint2*)h;
    }
    if (t < 128) { qbS[t] = qb[t]; kbS[t] = kb[t]; }
    __syncthreads();

    const int g8 = (lane >> 3) & 1, g16 = lane >> 4, l7 = lane & 7, tid4 = lane & 3;
    const uint32_t aBase  = sbF + (uint32_t)(((wr * 16 + l7 + g8 * 8) * RS + g16 * 8) * 2);
    const uint32_t aBase2 = sbQ + (uint32_t)(((wr * 16 + l7 + g8 * 8) * RS + g16 * 8) * 2);
    const uint32_t bBase  = sbW + (uint32_t)(((wc * 64 + l7 + g16 * 8) * RS + g8 * 8) * 2);
    const int r0 = wr * 16 + (lane >> 2);

    // ---- GEMM1 ----
    {
        float c[8][4];
        #pragma unroll
        for (int j = 0; j < 8; j++)
            #pragma unroll
            for (int q = 0; q < 4; q++) c[j][q] = 0.f;
        #pragma unroll
        for (int k = 0; k < 8; k++) {
            uint32_t a[4];
            ldsm4(a, aBase + k * 32);
            #pragma unroll
            for (int j2 = 0; j2 < 4; j2++) {
                uint32_t bb[4];
                ldsm4(bb, bBase + j2 * (16 * RS * 2) + k * 32);
                mma16816(c[2 * j2],     a, bb);
                mma16816(c[2 * j2 + 1], a, bb + 2);
            }
        }
        #pragma unroll
        for (int j = 0; j < 8; j++) {
            int col = wc * 64 + j * 8 + tid4 * 2;
            float b0 = qbS[col], b1 = qbS[col + 1];
            __half2 v0 = __floats2half2_rn(c[j][0] + b0, c[j][1] + b1);
            __half2 v1 = __floats2half2_rn(c[j][2] + b0, c[j][3] + b1);
            *(uint32_t*)(sQ + r0 * RS + col)       = *(uint32_t*)&v0;
            *(uint32_t*)(sQ + (r0 + 8) * RS + col) = *(uint32_t*)&v1;
            *(uint32_t*)(QH + ((size_t)b * NN + n0 + r0) * CH + col)     = *(uint32_t*)&v0;
            *(uint32_t*)(QH + ((size_t)b * NN + n0 + r0 + 8) * CH + col) = *(uint32_t*)&v1;
        }
    }

    __syncthreads();   // sQ complete; qW ldsm done
    #pragma unroll
    for (int it = 0; it < 16; it++) {   // kW fp32 -> fp16
        int idx = it * 256 + t;
        int r = idx >> 5, g = idx & 31;
        float4 w = *(const float4*)(kw + (size_t)r * CH + g * 4);
        __half h[4] = {__float2half(w.x), __float2half(w.y), __float2half(w.z), __float2half(w.w)};
        *(uint2*)(sW + r * RS + g * 4) = *(uint2*)h;
    }
    __syncthreads();

    // ---- GEMM2 ----
    {
        float c[8][4];
        #pragma unroll
        for (int j = 0; j < 8; j++)
            #pragma unroll
            for (int q = 0; q < 4; q++) c[j][q] = 0.f;
        #pragma unroll
        for (int k = 0; k < 8; k++) {
            uint32_t a[4];
            ldsm4(a, aBase2 + k * 32);
            #pragma unroll
            for (int j2 = 0; j2 < 4; j2++) {
                uint32_t bb[4];
                ldsm4(bb, bBase + j2 * (16 * RS * 2) + k * 32);
                mma16816(c[2 * j2],     a, bb);
                mma16816(c[2 * j2 + 1], a, bb + 2);
            }
        }
        #pragma unroll
        for (int j = 0; j < 8; j++) {
            int col = wc * 64 + j * 8 + tid4 * 2;
            float b0 = kbS[col], b1 = kbS[col + 1];
            __half2 v0 = __floats2half2_rn((c[j][0] + b0) * S2F, (c[j][1] + b1) * S2F);
            __half2 v1 = __floats2half2_rn((c[j][2] + b0) * S2F, (c[j][3] + b1) * S2F);
            *(uint32_t*)(KH + ((size_t)b * NN + n0 + r0) * CH + col)     = *(uint32_t*)&v0;
            *(uint32_t*)(KH + ((size_t)b * NN + n0 + r0 + 8) * CH + col) = *(uint32_t*)&v1;
        }
    }
}

// ---------------------------------------------------------------------------
// Stage 0 fat kernel: y<8 -> proj (b=y, 48 tiles of 64 rows, launched first);
// y>=8 -> flash<0> for batch y-8.
// ---------------------------------------------------------------------------
__global__ void __launch_bounds__(256, 3) stage0_kernel(
    const __half* __restrict__ f0h, const __half* __restrict__ f1h,
    const float* __restrict__ qw, const float* __restrict__ qb,
    const float* __restrict__ kw, const float* __restrict__ kb,
    __half* __restrict__ qh, __half* __restrict__ kh,
    float* __restrict__ flow_pred)
{
    extern __shared__ char smem[];
    if (blockIdx.y < 8)
        proj_body(f0h, qw, qb, kw, kb, qh, kh, blockIdx.y, blockIdx.x * 64, smem);
    else
        flash_body<0>(f0h, f1h, nullptr, flow_pred,
                      blockIdx.y - 8, blockIdx.x * 64, smem);
}

__global__ void __launch_bounds__(256, 3) stage1_kernel(
    const __half* __restrict__ qh, const __half* __restrict__ kh,
    const float* __restrict__ flow_pred, float* __restrict__ flow)
{
    extern __shared__ char smem[];
    flash_body<1>(qh, kh, flow_pred, flow, blockIdx.y, blockIdx.x * 64, smem);
}

__global__ void __launch_bounds__(256) convH2_kernel(
    const float* __restrict__ f0, const float* __restrict__ f1,
    __half* __restrict__ o0, __half* __restrict__ o1)
{
    __shared__ float tile[32][33];
    const int z = blockIdx.z, b = z & 7;
    const float* in = (z < 8) ? f0 : f1;
    __half* out = (z < 8) ? o0 : o1;
    const float scale = (z < 8) ? 1.0f : S2F;
    const int n0 = blockIdx.x * 32, c0 = blockIdx.y * 32;
    const int tx = threadIdx.x, ty = threadIdx.y;

    const float* ip = in + ((size_t)b * CH + c0) * NN + n0;
    #pragma unroll
    for (int i = 0; i < 4; i++) {
        int c = ty + i * 8;
        tile[c][tx] = ip[(size_t)c * NN + tx];
    }
    __syncthreads();
    __half* op = out + ((size_t)b * NN + n0) * CH + c0;
    #pragma unroll
    for (int i = 0; i < 4; i++) {
        int nr = ty + i * 8;
        op[(size_t)nr * CH + tx] = __float2half(tile[tx][nr] * scale);
    }
}

extern "C" void kernel_launch(void* const* d_in, const int* in_sizes, int n_in,
                              void* d_out, int out_size)
{
    const float* f0 = (const float*)d_in[0];
    const float* f1 = (const float*)d_in[1];
    const float* qw = (const float*)d_in[2];
    const float* qb = (const float*)d_in[3];
    const float* kw = (const float*)d_in[4];
    const float* kb = (const float*)d_in[5];

    float* out       = (float*)d_out;
    float* flow      = out;
    float* flow_pred = out + (size_t)BATCH * 2 * NN;

    void* p;
    cudaGetSymbolAddress(&p, g_f0h); __half* f0h = (__half*)p;
    cudaGetSymbolAddress(&p, g_f1h); __half* f1h = (__half*)p;
    cudaGetSymbolAddress(&p, g_qh);  __half* qh  = (__half*)p;
    cudaGetSymbolAddress(&p, g_kh);  __half* kh  = (__half*)p;

    cudaFuncSetAttribute(stage0_kernel, cudaFuncAttributeMaxDynamicSharedMemorySize, PSM_TOT);
    cudaFuncSetAttribute(stage1_kernel, cudaFuncAttributeMaxDynamicSharedMemorySize, FSM_TOT);

    dim3 cgrid(NN / 32, CH / 32, 2 * BATCH);
    dim3 cblk(32, 8);
    dim3 s0grid(NN / 64, 2 * BATCH);   // y 0..7 proj, y 8..15 flash
    dim3 s1grid(NN / 64, BATCH);

    convH2_kernel<<<cgrid, cblk>>>(f0, f1, f0h, f1h);
    stage0_kernel<<<s0grid, 256, PSM_TOT>>>(f0h, f1h, qw, qb, kw, kb, qh, kh, flow_pred);
    stage1_kernel<<<s1grid, 256, FSM_TOT>>>(qh, kh, flow_pred, flow);
}

// round 8
// speedup vs baseline: 1.0761x; 1.0761x over previous
#include <cuda_runtime.h>
#include <cuda_fp16.h>
#include <cstdint>

#define BATCH 8
#define CH    128
#define HH    48
#define WW    64
#define NN    (HH*WW)   // 3072

#define S2F ((float)(1.4426950408889634 * 0.088388347648318447))

__device__ __half g_f0h[BATCH*NN*CH];
__device__ __half g_f1h[BATCH*NN*CH];
__device__ __half g_qh [BATCH*NN*CH];
__device__ __half g_kh [BATCH*NN*CH];

__device__ __forceinline__ uint32_t smem_u32(const void* p) {
    uint32_t a;
    asm("{ .reg .u64 t; cvta.to.shared.u64 t, %1; cvt.u32.u64 %0, t; }" : "=r"(a) : "l"(p));
    return a;
}
__device__ __forceinline__ void ldsm4(uint32_t* r, uint32_t addr) {
    asm volatile("ldmatrix.sync.aligned.m8n8.x4.shared.b16 {%0,%1,%2,%3}, [%4];"
        : "=r"(r[0]), "=r"(r[1]), "=r"(r[2]), "=r"(r[3]) : "r"(addr));
}
__device__ __forceinline__ void mma16816(float* c, const uint32_t* a, const uint32_t* b) {
    asm volatile("mma.sync.aligned.m16n8k16.row.col.f32.f16.f16.f32 "
        "{%0,%1,%2,%3}, {%4,%5,%6,%7}, {%8,%9}, {%0,%1,%2,%3};"
        : "+f"(c[0]), "+f"(c[1]), "+f"(c[2]), "+f"(c[3])
        : "r"(a[0]), "r"(a[1]), "r"(a[2]), "r"(a[3]), "r"(b[0]), "r"(b[1]));
}
__device__ __forceinline__ float ex2f(float x) {
    float y; asm("ex2.approx.f32 %0, %1;" : "=f"(y) : "f"(x)); return y;
}
#define CP16(dst, src) asm volatile("cp.async.cg.shared.global [%0], [%1], 16;" :: "r"(dst), "l"(src))
#define CP_COMMIT()    asm volatile("cp.async.commit_group;" ::: "memory")
#define CP_WAIT0()     asm volatile("cp.async.wait_group 0;" ::: "memory")

#define RS 136

// Flash smem map: 64-query A tile, double-buffered 128-key B tiles (R6 layout)
#define FSM_A    0          // 64*RS*2 = 17408
#define FSM_B0   17408      // 128*RS*2 = 34816
#define FSM_B1   52224
#define FSM_V0   87040      // 1 KB (128 x + 128 y floats)
#define FSM_V1   88064
#define FSM_RED  89088      // 192 floats
#define FSM_TOT  90112

// Proj smem map (128-row tile, register-chained q->k; runs inside stage0)
#define PSM_F   0
#define PSM_W   34816
#define PSM_QB  69632
#define PSM_KB  70144

// 128-row fp16 tile prefetch (RS stride)
__device__ __forceinline__ void prefetch_tile(uint32_t dstBase, const __half* src, int t) {
    #pragma unroll
    for (int it = 0; it < 8; it++) {
        int idx = it * 256 + t;
        int r = idx >> 4, g = idx & 15;
        CP16(dstBase + (uint32_t)((r * RS + g * 8) * 2), src + (size_t)r * CH + g * 8);
    }
}

// ---------------------------------------------------------------------------
// Flash body: 64-query tile, 24 key tiles of 128, cp.async double buffer.
// Warp tile: 16 queries (wr) x 64 keys (wc half); wc pair merged via smem.
// A-operand fragments hoisted out of the key-tile loop (loop-invariant).
// MODE 0: V = grid coords; MODE 1: V = vsrc fp32 [B][2][N].
// ---------------------------------------------------------------------------
template<int MODE>
__device__ __forceinline__ void flash_body(
    const __half* __restrict__ A, const __half* __restrict__ Bm,
    const float* __restrict__ vsrc, float* __restrict__ out,
    int b, int n0, char* smem)
{
    const uint32_t sb = smem_u32(smem);
    const int t = threadIdx.x, wid = t >> 5, lane = t & 31;
    const int wr = wid >> 1, wc = wid & 1;
    const size_t vbase = (size_t)b * 2 * NN;

    {   // query tile: 64 rows (plain stores; ordered by the sync below)
        __half* sA = (__half*)smem;
        const __half* src = A + ((size_t)b * NN + n0) * CH;
        #pragma unroll
        for (int it = 0; it < 4; it++) {
            int idx = it * 256 + t;
            int r = idx >> 4, g = idx & 15;
            *(uint4*)(sA + r * RS + g * 8) = *(const uint4*)(src + (size_t)r * CH + g * 8);
        }
    }

    const __half* Bbase = Bm + (size_t)b * NN * CH;
    prefetch_tile(sb + FSM_B0, Bbase, t);
    if (MODE == 1 && t < 64) {
        const float* s = (t < 32) ? (vsrc + vbase + t * 4)
                                  : (vsrc + vbase + NN + (t - 32) * 4);
        CP16(sb + FSM_V0 + t * 16, s);
    }
    CP_COMMIT();

    const int g8 = (lane >> 3) & 1, g16 = lane >> 4, l7 = lane & 7, tid4 = lane & 3;
    const uint32_t aBase = sb + FSM_A + (uint32_t)(((wr * 16 + l7 + g8 * 8) * RS + g16 * 8) * 2);
    const uint32_t bOff  = (uint32_t)(((wc * 64 + l7 + g16 * 8) * RS + g8 * 8) * 2);

    // Tile-0 data + sA ready; hoist all A fragments (loop-invariant)
    CP_WAIT0();
    __syncthreads();
    uint32_t aF[8][4];
    #pragma unroll
    for (int k = 0; k < 8; k++) ldsm4(aF[k], aBase + k * 32);

    // Prefetch tile 1 into B1
    if (1 < NN / 128) {
        prefetch_tile(sb + FSM_B1, Bbase + (size_t)128 * CH, t);
        if (MODE == 1 && t < 64) {
            const float* s = (t < 32) ? (vsrc + vbase + 128 + t * 4)
                                      : (vsrc + vbase + NN + 128 + (t - 32) * 4);
            CP16(sb + FSM_V1 + t * 16, s);
        }
        CP_COMMIT();
    }

    float L[2] = {0.f, 0.f}, AX[2] = {0.f, 0.f}, AY[2] = {0.f, 0.f};

    for (int tile = 0; tile < NN / 128; tile++) {
        const uint32_t cur = tile & 1;
        if (tile > 0) {
            CP_WAIT0();       // buffer for this tile ready
            __syncthreads();  // all warps done with the buffer being refilled
            if (tile + 1 < NN / 128) {
                const int mn = (tile + 1) * 128;
                prefetch_tile(sb + (cur ? FSM_B0 : FSM_B1), Bbase + (size_t)mn * CH, t);
                if (MODE == 1 && t < 64) {
                    const float* s = (t < 32) ? (vsrc + vbase + mn + t * 4)
                                              : (vsrc + vbase + NN + mn + (t - 32) * 4);
                    CP16(sb + (cur ? FSM_V0 : FSM_V1) + t * 16, s);
                }
                CP_COMMIT();
            }
        }

        const uint32_t bB = sb + (cur ? FSM_B1 : FSM_B0) + bOff;
        const float* sV = (const float*)(smem + (cur ? FSM_V1 : FSM_V0));

        float c[8][4];
        #pragma unroll
        for (int j = 0; j < 8; j++)
            #pragma unroll
            for (int q = 0; q < 4; q++) c[j][q] = 0.f;

        #pragma unroll
        for (int k = 0; k < 8; k++) {
            #pragma unroll
            for (int j2 = 0; j2 < 4; j2++) {
                uint32_t bb[4];
                ldsm4(bb, bB + j2 * (16 * RS * 2) + k * 32);
                mma16816(c[2 * j2],     aF[k], bb);
                mma16816(c[2 * j2 + 1], aF[k], bb + 2);
            }
        }

        float Lt0 = 0.f, Lt1 = 0.f;
        #pragma unroll
        for (int j = 0; j < 8; j++) {
            float p0 = ex2f(c[j][0]);
            float p1 = ex2f(c[j][1]);
            float p2 = ex2f(c[j][2]);
            float p3 = ex2f(c[j][3]);
            if (MODE == 0) {
                float vx0 = (float)(j * 8 + tid4 * 2);  // (m & 63), wc-independent
                float vx1 = vx0 + 1.f;
                Lt0 += p0 + p1;  Lt1 += p2 + p3;
                AX[0] += p0 * vx0 + p1 * vx1;
                AX[1] += p2 * vx0 + p3 * vx1;
            } else {
                int cl = wc * 64 + j * 8 + tid4 * 2;
                float2 x2 = *(const float2*)&sV[cl];
                float2 y2 = *(const float2*)&sV[128 + cl];
                L[0]  += p0 + p1;          L[1]  += p2 + p3;
                AX[0] += p0 * x2.x + p1 * x2.y;
                AX[1] += p2 * x2.x + p3 * x2.y;
                AY[0] += p0 * y2.x + p1 * y2.y;
                AY[1] += p2 * y2.x + p3 * y2.y;
            }
        }
        if (MODE == 0) {
            float vy = (float)(2 * tile + wc);   // 128-key tile = 2 grid rows
            L[0] += Lt0;  L[1] += Lt1;
            AY[0] += vy * Lt0;  AY[1] += vy * Lt1;
        }
    }

    #pragma unroll
    for (int o = 1; o <= 2; o <<= 1)
        #pragma unroll
        for (int h = 0; h < 2; h++) {
            L[h]  += __shfl_xor_sync(0xffffffffu, L[h],  o);
            AX[h] += __shfl_xor_sync(0xffffffffu, AX[h], o);
            AY[h] += __shfl_xor_sync(0xffffffffu, AY[h], o);
        }

    float* red = (float*)(smem + FSM_RED);
    __syncthreads();   // mainloop consumers done before RED reuse is safe
    if (wc == 1 && tid4 == 0) {
        #pragma unroll
        for (int h = 0; h < 2; h++) {
            int rl = wr * 16 + h * 8 + (lane >> 2);
            red[rl]       = L[h];
            red[64 + rl]  = AX[h];
            red[128 + rl] = AY[h];
        }
    }
    __syncthreads();
    if (wc == 0 && tid4 == 0) {
        float* ob = out + vbase;
        #pragma unroll
        for (int h = 0; h < 2; h++) {
            int rl = wr * 16 + h * 8 + (lane >> 2);
            float Lt  = L[h]  + red[rl];
            float AXt = AX[h] + red[64 + rl];
            float AYt = AY[h] + red[128 + rl];
            int n = n0 + rl;
            float fx = AXt / Lt, fy = AYt / Lt;
            if (MODE == 0) { fx -= (float)(n & (WW - 1)); fy -= (float)(n >> 6); }
            ob[n] = fx;  ob[NN + n] = fy;
        }
    }
}

// ---------------------------------------------------------------------------
// Proj body (R6): 128-row tile; q kept in registers as GEMM2 A-fragments.
// ---------------------------------------------------------------------------
__device__ __forceinline__ void proj_body(
    const __half* __restrict__ F0, const float* __restrict__ qw,
    const float* __restrict__ qb,  const float* __restrict__ kw,
    const float* __restrict__ kb,
    __half* __restrict__ QH, __half* __restrict__ KH,
    int b, int n0, char* smem)
{
    __half* sF = (__half*)(smem + PSM_F);
    __half* sW = (__half*)(smem + PSM_W);
    float* qbS = (float*)(smem + PSM_QB);
    float* kbS = (float*)(smem + PSM_KB);
    const uint32_t sbF = smem_u32(sF), sbW = smem_u32(sW);

    const int t = threadIdx.x, wid = t >> 5, lane = t & 31;

    {
        const __half* src = F0 + ((size_t)b * NN + n0) * CH;
        #pragma unroll
        for (int it = 0; it < 8; it++) {
            int idx = it * 256 + t;
            int r = idx >> 4, g = idx & 15;
            *(uint4*)(sF + r * RS + g * 8) = *(const uint4*)(src + (size_t)r * CH + g * 8);
        }
    }
    #pragma unroll
    for (int it = 0; it < 16; it++) {
        int idx = it * 256 + t;
        int r = idx >> 5, g = idx & 31;
        float4 w = *(const float4*)(qw + (size_t)r * CH + g * 4);
        __half h[4] = {__float2half(w.x), __float2half(w.y), __float2half(w.z), __float2half(w.w)};
        *(uint2*)(sW + r * RS + g * 4) = *(uint2*)h;
    }
    if (t < 128) { qbS[t] = qb[t]; kbS[t] = kb[t]; }
    __syncthreads();

    const int g8 = (lane >> 3) & 1, g16 = lane >> 4, l7 = lane & 7, tid4 = lane & 3;
    const uint32_t aBase = sbF + (uint32_t)(((wid * 16 + l7 + g8 * 8) * RS + g16 * 8) * 2);
    const uint32_t bBase = sbW + (uint32_t)(((l7 + g16 * 8) * RS + g8 * 8) * 2);

    float c[16][4];
    #pragma unroll
    for (int j = 0; j < 16; j++)
        #pragma unroll
        for (int q = 0; q < 4; q++) c[j][q] = 0.f;
    #pragma unroll
    for (int k = 0; k < 8; k++) {
        uint32_t a[4];
        ldsm4(a, aBase + k * 32);
        #pragma unroll
        for (int j2 = 0; j2 < 8; j2++) {
            uint32_t bb[4];
            ldsm4(bb, bBase + j2 * (16 * RS * 2) + k * 32);
            mma16816(c[2 * j2],     a, bb);
            mma16816(c[2 * j2 + 1], a, bb + 2);
        }
    }

    uint32_t hq[16][2];
    const int r0 = wid * 16 + (lane >> 2);
    #pragma unroll
    for (int j = 0; j < 16; j++) {
        int col = j * 8 + tid4 * 2;
        float b0 = qbS[col], b1 = qbS[col + 1];
        __half2 v0 = __floats2half2_rn(c[j][0] + b0, c[j][1] + b1);
        __half2 v1 = __floats2half2_rn(c[j][2] + b0, c[j][3] + b1);
        hq[j][0] = *(uint32_t*)&v0;
        hq[j][1] = *(uint32_t*)&v1;
        *(uint32_t*)(QH + ((size_t)b * NN + n0 + r0) * CH + col)     = hq[j][0];
        *(uint32_t*)(QH + ((size_t)b * NN + n0 + r0 + 8) * CH + col) = hq[j][1];
    }

    __syncthreads();
    #pragma unroll
    for (int it = 0; it < 16; it++) {
        int idx = it * 256 + t;
        int r = idx >> 5, g = idx & 31;
        float4 w = *(const float4*)(kw + (size_t)r * CH + g * 4);
        __half h[4] = {__float2half(w.x), __float2half(w.y), __float2half(w.z), __float2half(w.w)};
        *(uint2*)(sW + r * RS + g * 4) = *(uint2*)h;
    }
    __syncthreads();

    float c2[16][4];
    #pragma unroll
    for (int j = 0; j < 16; j++)
        #pragma unroll
        for (int q = 0; q < 4; q++) c2[j][q] = 0.f;
    #pragma unroll
    for (int kk = 0; kk < 8; kk++) {
        uint32_t a[4] = { hq[2 * kk][0], hq[2 * kk][1], hq[2 * kk + 1][0], hq[2 * kk + 1][1] };
        #pragma unroll
        for (int j2 = 0; j2 < 8; j2++) {
            uint32_t bb[4];
            ldsm4(bb, bBase + j2 * (16 * RS * 2) + kk * 32);
            mma16816(c2[2 * j2],     a, bb);
            mma16816(c2[2 * j2 + 1], a, bb + 2);
        }
    }
    #pragma unroll
    for (int j = 0; j < 16; j++) {
        int col = j * 8 + tid4 * 2;
        float b0 = kbS[col], b1 = kbS[col + 1];
        __half2 v0 = __floats2half2_rn((c2[j][0] + b0) * S2F, (c2[j][1] + b1) * S2F);
        __half2 v1 = __floats2half2_rn((c2[j][2] + b0) * S2F, (c2[j][3] + b1) * S2F);
        *(uint32_t*)(KH + ((size_t)b * NN + n0 + r0) * CH + col)     = *(uint32_t*)&v0;
        *(uint32_t*)(KH + ((size_t)b * NN + n0 + r0 + 8) * CH + col) = *(uint32_t*)&v1;
    }
}

__global__ void __launch_bounds__(256, 2) stage0_kernel(
    const __half* __restrict__ f0h, const __half* __restrict__ f1h,
    const float* __restrict__ qw, const float* __restrict__ qb,
    const float* __restrict__ kw, const float* __restrict__ kb,
    __half* __restrict__ qh, __half* __restrict__ kh,
    float* __restrict__ flow_pred)
{
    extern __shared__ char smem[];
    if (blockIdx.y < 4) {                        // 192 proj CTAs, scheduled first
        int idx = blockIdx.y * 48 + blockIdx.x;  // 0..191
        proj_body(f0h, qw, qb, kw, kb, qh, kh, idx / 24, (idx % 24) * 128, smem);
    } else {
        flash_body<0>(f0h, f1h, nullptr, flow_pred,
                      blockIdx.y - 4, blockIdx.x * 64, smem);
    }
}

__global__ void __launch_bounds__(256, 2) stage1_kernel(
    const __half* __restrict__ qh, const __half* __restrict__ kh,
    const float* __restrict__ flow_pred, float* __restrict__ flow)
{
    extern __shared__ char smem[];
    flash_body<1>(qh, kh, flow_pred, flow, blockIdx.y, blockIdx.x * 64, smem);
}

__global__ void __launch_bounds__(256) convH2_kernel(
    const float* __restrict__ f0, const float* __restrict__ f1,
    __half* __restrict__ o0, __half* __restrict__ o1)
{
    __shared__ float tile[32][33];
    const int z = blockIdx.z, b = z & 7;
    const float* in = (z < 8) ? f0 : f1;
    __half* out = (z < 8) ? o0 : o1;
    const float scale = (z < 8) ? 1.0f : S2F;
    const int n0 = blockIdx.x * 32, c0 = blockIdx.y * 32;
    const int tx = threadIdx.x, ty = threadIdx.y;

    const float* ip = in + ((size_t)b * CH + c0) * NN + n0;
    #pragma unroll
    for (int i = 0; i < 4; i++) {
        int c = ty + i * 8;
        tile[c][tx] = ip[(size_t)c * NN + tx];
    }
    __syncthreads();
    __half* op = out + ((size_t)b * NN + n0) * CH + c0;
    #pragma unroll
    for (int i = 0; i < 4; i++) {
        int nr = ty + i * 8;
        op[(size_t)nr * CH + tx] = __float2half(tile[tx][nr] * scale);
    }
}

extern "C" void kernel_launch(void* const* d_in, const int* in_sizes, int n_in,
                              void* d_out, int out_size)
{
    const float* f0 = (const float*)d_in[0];
    const float* f1 = (const float*)d_in[1];
    const float* qw = (const float*)d_in[2];
    const float* qb = (const float*)d_in[3];
    const float* kw = (const float*)d_in[4];
    const float* kb = (const float*)d_in[5];

    float* out       = (float*)d_out;
    float* flow      = out;
    float* flow_pred = out + (size_t)BATCH * 2 * NN;

    void* p;
    cudaGetSymbolAddress(&p, g_f0h); __half* f0h = (__half*)p;
    cudaGetSymbolAddress(&p, g_f1h); __half* f1h = (__half*)p;
    cudaGetSymbolAddress(&p, g_qh);  __half* qh  = (__half*)p;
    cudaGetSymbolAddress(&p, g_kh);  __half* kh  = (__half*)p;

    cudaFuncSetAttribute(stage0_kernel, cudaFuncAttributeMaxDynamicSharedMemorySize, FSM_TOT);
    cudaFuncSetAttribute(stage1_kernel, cudaFuncAttributeMaxDynamicSharedMemorySize, FSM_TOT);

    dim3 cgrid(NN / 32, CH / 32, 2 * BATCH);
    dim3 cblk(32, 8);
    dim3 s0grid(NN / 64, BATCH + 4);   // y 0..3 proj, y 4..11 flash
    dim3 s1grid(NN / 64, BATCH);

    convH2_kernel<<<cgrid, cblk>>>(f0, f1, f0h, f1h);
    stage0_kernel<<<s0grid, 256, FSM_TOT>>>(f0h, f1h, qw, qb, kw, kb, qh, kh, flow_pred);
    stage1_kernel<<<s1grid, 256, FSM_TOT>>>(qh, kh, flow_pred, flow);
}

// round 9
// speedup vs baseline: 1.1283x; 1.0485x over previous
#include <cuda_runtime.h>
#include <cuda_fp16.h>
#include <cstdint>

#define BATCH 8
#define CH    128
#define HH    48
#define WW    64
#define NN    (HH*WW)   // 3072

#define S2F ((float)(1.4426950408889634 * 0.088388347648318447))

__device__ __half g_f0h[BATCH*NN*CH];
__device__ __half g_f1h[BATCH*NN*CH];
__device__ __half g_qh [BATCH*NN*CH];
__device__ __half g_kh [BATCH*NN*CH];
__device__ int    g_done[BATCH];       // stage0 completions per batch (target 72)

__device__ __forceinline__ uint32_t smem_u32(const void* p) {
    uint32_t a;
    asm("{ .reg .u64 t; cvta.to.shared.u64 t, %1; cvt.u32.u64 %0, t; }" : "=r"(a) : "l"(p));
    return a;
}
__device__ __forceinline__ void ldsm4(uint32_t* r, uint32_t addr) {
    asm volatile("ldmatrix.sync.aligned.m8n8.x4.shared.b16 {%0,%1,%2,%3}, [%4];"
        : "=r"(r[0]), "=r"(r[1]), "=r"(r[2]), "=r"(r[3]) : "r"(addr));
}
__device__ __forceinline__ void mma16816(float* c, const uint32_t* a, const uint32_t* b) {
    asm volatile("mma.sync.aligned.m16n8k16.row.col.f32.f16.f16.f32 "
        "{%0,%1,%2,%3}, {%4,%5,%6,%7}, {%8,%9}, {%0,%1,%2,%3};"
        : "+f"(c[0]), "+f"(c[1]), "+f"(c[2]), "+f"(c[3])
        : "r"(a[0]), "r"(a[1]), "r"(a[2]), "r"(a[3]), "r"(b[0]), "r"(b[1]));
}
__device__ __forceinline__ float ex2f(float x) {
    float y; asm("ex2.approx.f32 %0, %1;" : "=f"(y) : "f"(x)); return y;
}
#define CP16(dst, src) asm volatile("cp.async.cg.shared.global [%0], [%1], 16;" :: "r"(dst), "l"(src))
#define CP_COMMIT()    asm volatile("cp.async.commit_group;" ::: "memory")
#define CP_WAIT0()     asm volatile("cp.async.wait_group 0;" ::: "memory")

#define RS 136

// Flash smem map: 64-query A tile, double-buffered 128-key B tiles
#define FSM_A    0          // 64*RS*2 = 17408
#define FSM_B0   17408      // 128*RS*2 = 34816
#define FSM_B1   52224
#define FSM_V0   87040      // 1 KB
#define FSM_V1   88064
#define FSM_RED  89088      // 192 floats
#define FSM_TOT  90112

// Proj smem map (fits inside FSM_TOT)
#define PSM_F   0
#define PSM_W   34816
#define PSM_QB  69632
#define PSM_KB  70144

__device__ __forceinline__ void prefetch_tile(uint32_t dstBase, const __half* src, int t) {
    #pragma unroll
    for (int it = 0; it < 8; it++) {
        int idx = it * 256 + t;
        int r = idx >> 4, g = idx & 15;
        CP16(dstBase + (uint32_t)((r * RS + g * 8) * 2), src + (size_t)r * CH + g * 8);
    }
}

// ---------------------------------------------------------------------------
// Flash body (R8 winner): 64-query tile, 24 key tiles of 128, double buffer,
// A-fragments hoisted. Warp tile 16q x 64k (wc half), wc pair merged via smem.
// ---------------------------------------------------------------------------
template<int MODE>
__device__ __forceinline__ void flash_body(
    const __half* __restrict__ A, const __half* __restrict__ Bm,
    const float* __restrict__ vsrc, float* __restrict__ out,
    int b, int n0, char* smem)
{
    const uint32_t sb = smem_u32(smem);
    const int t = threadIdx.x, wid = t >> 5, lane = t & 31;
    const int wr = wid >> 1, wc = wid & 1;
    const size_t vbase = (size_t)b * 2 * NN;

    {   // query tile: 64 rows
        __half* sA = (__half*)smem;
        const __half* src = A + ((size_t)b * NN + n0) * CH;
        #pragma unroll
        for (int it = 0; it < 4; it++) {
            int idx = it * 256 + t;
            int r = idx >> 4, g = idx & 15;
            *(uint4*)(sA + r * RS + g * 8) = *(const uint4*)(src + (size_t)r * CH + g * 8);
        }
    }

    const __half* Bbase = Bm + (size_t)b * NN * CH;
    prefetch_tile(sb + FSM_B0, Bbase, t);
    if (MODE == 1 && t < 64) {
        const float* s = (t < 32) ? (vsrc + vbase + t * 4)
                                  : (vsrc + vbase + NN + (t - 32) * 4);
        CP16(sb + FSM_V0 + t * 16, s);
    }
    CP_COMMIT();

    const int g8 = (lane >> 3) & 1, g16 = lane >> 4, l7 = lane & 7, tid4 = lane & 3;
    const uint32_t aBase = sb + FSM_A + (uint32_t)(((wr * 16 + l7 + g8 * 8) * RS + g16 * 8) * 2);
    const uint32_t bOff  = (uint32_t)(((wc * 64 + l7 + g16 * 8) * RS + g8 * 8) * 2);

    CP_WAIT0();
    __syncthreads();
    uint32_t aF[8][4];
    #pragma unroll
    for (int k = 0; k < 8; k++) ldsm4(aF[k], aBase + k * 32);

    prefetch_tile(sb + FSM_B1, Bbase + (size_t)128 * CH, t);
    if (MODE == 1 && t < 64) {
        const float* s = (t < 32) ? (vsrc + vbase + 128 + t * 4)
                                  : (vsrc + vbase + NN + 128 + (t - 32) * 4);
        CP16(sb + FSM_V1 + t * 16, s);
    }
    CP_COMMIT();

    float L[2] = {0.f, 0.f}, AX[2] = {0.f, 0.f}, AY[2] = {0.f, 0.f};

    for (int tile = 0; tile < NN / 128; tile++) {
        const uint32_t cur = tile & 1;
        if (tile > 0) {
            CP_WAIT0();
            __syncthreads();
            if (tile + 1 < NN / 128) {
                const int mn = (tile + 1) * 128;
                prefetch_tile(sb + (cur ? FSM_B0 : FSM_B1), Bbase + (size_t)mn * CH, t);
                if (MODE == 1 && t < 64) {
                    const float* s = (t < 32) ? (vsrc + vbase + mn + t * 4)
                                              : (vsrc + vbase + NN + mn + (t - 32) * 4);
                    CP16(sb + (cur ? FSM_V0 : FSM_V1) + t * 16, s);
                }
                CP_COMMIT();
            }
        }

        const uint32_t bB = sb + (cur ? FSM_B1 : FSM_B0) + bOff;
        const float* sV = (const float*)(smem + (cur ? FSM_V1 : FSM_V0));

        float c[8][4];
        #pragma unroll
        for (int j = 0; j < 8; j++)
            #pragma unroll
            for (int q = 0; q < 4; q++) c[j][q] = 0.f;

        #pragma unroll
        for (int k = 0; k < 8; k++) {
            #pragma unroll
            for (int j2 = 0; j2 < 4; j2++) {
                uint32_t bb[4];
                ldsm4(bb, bB + j2 * (16 * RS * 2) + k * 32);
                mma16816(c[2 * j2],     aF[k], bb);
                mma16816(c[2 * j2 + 1], aF[k], bb + 2);
            }
        }

        float Lt0 = 0.f, Lt1 = 0.f;
        #pragma unroll
        for (int j = 0; j < 8; j++) {
            float p0 = ex2f(c[j][0]);
            float p1 = ex2f(c[j][1]);
            float p2 = ex2f(c[j][2]);
            float p3 = ex2f(c[j][3]);
            if (MODE == 0) {
                float vx0 = (float)(j * 8 + tid4 * 2);
                float vx1 = vx0 + 1.f;
                Lt0 += p0 + p1;  Lt1 += p2 + p3;
                AX[0] += p0 * vx0 + p1 * vx1;
                AX[1] += p2 * vx0 + p3 * vx1;
            } else {
                int cl = wc * 64 + j * 8 + tid4 * 2;
                float2 x2 = *(const float2*)&sV[cl];
                float2 y2 = *(const float2*)&sV[128 + cl];
                L[0]  += p0 + p1;          L[1]  += p2 + p3;
                AX[0] += p0 * x2.x + p1 * x2.y;
                AX[1] += p2 * x2.x + p3 * x2.y;
                AY[0] += p0 * y2.x + p1 * y2.y;
                AY[1] += p2 * y2.x + p3 * y2.y;
            }
        }
        if (MODE == 0) {
            float vy = (float)(2 * tile + wc);
            L[0] += Lt0;  L[1] += Lt1;
            AY[0] += vy * Lt0;  AY[1] += vy * Lt1;
        }
    }

    #pragma unroll
    for (int o = 1; o <= 2; o <<= 1)
        #pragma unroll
        for (int h = 0; h < 2; h++) {
            L[h]  += __shfl_xor_sync(0xffffffffu, L[h],  o);
            AX[h] += __shfl_xor_sync(0xffffffffu, AX[h], o);
            AY[h] += __shfl_xor_sync(0xffffffffu, AY[h], o);
        }

    float* red = (float*)(smem + FSM_RED);
    __syncthreads();
    if (wc == 1 && tid4 == 0) {
        #pragma unroll
        for (int h = 0; h < 2; h++) {
            int rl = wr * 16 + h * 8 + (lane >> 2);
            red[rl]       = L[h];
            red[64 + rl]  = AX[h];
            red[128 + rl] = AY[h];
        }
    }
    __syncthreads();
    if (wc == 0 && tid4 == 0) {
        float* ob = out + vbase;
        #pragma unroll
        for (int h = 0; h < 2; h++) {
            int rl = wr * 16 + h * 8 + (lane >> 2);
            float Lt  = L[h]  + red[rl];
            float AXt = AX[h] + red[64 + rl];
            float AYt = AY[h] + red[128 + rl];
            int n = n0 + rl;
            float fx = AXt / Lt, fy = AYt / Lt;
            if (MODE == 0) { fx -= (float)(n & (WW - 1)); fy -= (float)(n >> 6); }
            ob[n] = fx;  ob[NN + n] = fy;
        }
    }
}

// ---------------------------------------------------------------------------
// Proj body (R8): 128-row tile; q kept in registers as GEMM2 A-fragments.
// ---------------------------------------------------------------------------
__device__ __forceinline__ void proj_body(
    const __half* __restrict__ F0, const float* __restrict__ qw,
    const float* __restrict__ qb,  const float* __restrict__ kw,
    const float* __restrict__ kb,
    __half* __restrict__ QH, __half* __restrict__ KH,
    int b, int n0, char* smem)
{
    __half* sF = (__half*)(smem + PSM_F);
    __half* sW = (__half*)(smem + PSM_W);
    float* qbS = (float*)(smem + PSM_QB);
    float* kbS = (float*)(smem + PSM_KB);
    const uint32_t sbF = smem_u32(sF), sbW = smem_u32(sW);

    const int t = threadIdx.x, wid = t >> 5, lane = t & 31;

    {
        const __half* src = F0 + ((size_t)b * NN + n0) * CH;
        #pragma unroll
        for (int it = 0; it < 8; it++) {
            int idx = it * 256 + t;
            int r = idx >> 4, g = idx & 15;
            *(uint4*)(sF + r * RS + g * 8) = *(const uint4*)(src + (size_t)r * CH + g * 8);
        }
    }
    #pragma unroll
    for (int it = 0; it < 16; it++) {
        int idx = it * 256 + t;
        int r = idx >> 5, g = idx & 31;
        float4 w = *(const float4*)(qw + (size_t)r * CH + g * 4);
        __half h[4] = {__float2half(w.x), __float2half(w.y), __float2half(w.z), __float2half(w.w)};
        *(uint2*)(sW + r * RS + g * 4) = *(uint2*)h;
    }
    if (t < 128) { qbS[t] = qb[t]; kbS[t] = kb[t]; }
    __syncthreads();

    const int g8 = (lane >> 3) & 1, g16 = lane >> 4, l7 = lane & 7, tid4 = lane & 3;
    const uint32_t aBase = sbF + (uint32_t)(((wid * 16 + l7 + g8 * 8) * RS + g16 * 8) * 2);
    const uint32_t bBase = sbW + (uint32_t)(((l7 + g16 * 8) * RS + g8 * 8) * 2);

    float c[16][4];
    #pragma unroll
    for (int j = 0; j < 16; j++)
        #pragma unroll
        for (int q = 0; q < 4; q++) c[j][q] = 0.f;
    #pragma unroll
    for (int k = 0; k < 8; k++) {
        uint32_t a[4];
        ldsm4(a, aBase + k * 32);
        #pragma unroll
        for (int j2 = 0; j2 < 8; j2++) {
            uint32_t bb[4];
            ldsm4(bb, bBase + j2 * (16 * RS * 2) + k * 32);
            mma16816(c[2 * j2],     a, bb);
            mma16816(c[2 * j2 + 1], a, bb + 2);
        }
    }

    uint32_t hq[16][2];
    const int r0 = wid * 16 + (lane >> 2);
    #pragma unroll
    for (int j = 0; j < 16; j++) {
        int col = j * 8 + tid4 * 2;
        float b0 = qbS[col], b1 = qbS[col + 1];
        __half2 v0 = __floats2half2_rn(c[j][0] + b0, c[j][1] + b1);
        __half2 v1 = __floats2half2_rn(c[j][2] + b0, c[j][3] + b1);
        hq[j][0] = *(uint32_t*)&v0;
        hq[j][1] = *(uint32_t*)&v1;
        *(uint32_t*)(QH + ((size_t)b * NN + n0 + r0) * CH + col)     = hq[j][0];
        *(uint32_t*)(QH + ((size_t)b * NN + n0 + r0 + 8) * CH + col) = hq[j][1];
    }

    __syncthreads();
    #pragma unroll
    for (int it = 0; it < 16; it++) {
        int idx = it * 256 + t;
        int r = idx >> 5, g = idx & 31;
        float4 w = *(const float4*)(kw + (size_t)r * CH + g * 4);
        __half h[4] = {__float2half(w.x), __float2half(w.y), __float2half(w.z), __float2half(w.w)};
        *(uint2*)(sW + r * RS + g * 4) = *(uint2*)h;
    }
    __syncthreads();

    float c2[16][4];
    #pragma unroll
    for (int j = 0; j < 16; j++)
        #pragma unroll
        for (int q = 0; q < 4; q++) c2[j][q] = 0.f;
    #pragma unroll
    for (int kk = 0; kk < 8; kk++) {
        uint32_t a[4] = { hq[2 * kk][0], hq[2 * kk][1], hq[2 * kk + 1][0], hq[2 * kk + 1][1] };
        #pragma unroll
        for (int j2 = 0; j2 < 8; j2++) {
            uint32_t bb[4];
            ldsm4(bb, bBase + j2 * (16 * RS * 2) + kk * 32);
            mma16816(c2[2 * j2],     a, bb);
            mma16816(c2[2 * j2 + 1], a, bb + 2);
        }
    }
    #pragma unroll
    for (int j = 0; j < 16; j++) {
        int col = j * 8 + tid4 * 2;
        float b0 = kbS[col], b1 = kbS[col + 1];
        __half2 v0 = __floats2half2_rn((c2[j][0] + b0) * S2F, (c2[j][1] + b1) * S2F);
        __half2 v1 = __floats2half2_rn((c2[j][2] + b0) * S2F, (c2[j][3] + b1) * S2F);
        *(uint32_t*)(KH + ((size_t)b * NN + n0 + r0) * CH + col)     = *(uint32_t*)&v0;
        *(uint32_t*)(KH + ((size_t)b * NN + n0 + r0 + 8) * CH + col) = *(uint32_t*)&v1;
    }
}

// ---------------------------------------------------------------------------
// Fused pipeline kernel. 1-D grid of 960 CTAs, dispatched in bid order:
//   bid   0..191 : proj   (b = idx/24, n0 = (idx%24)*128)  -> g_done[b] +=1
//   bid 192..575 : flash0 (b = idx/48, n0 = (idx%48)*64)   -> g_done[b] +=1
//   bid 576..959 : flash1 — spins until g_done[b] == 72 (24 proj + 48 flash0),
//                  then runs. Forward progress: a flash1 CTA is only resident
//                  after >=280 lower-bid stage0 CTAs retired; everything it
//                  waits on is resident-or-done.
// g_done[] is zeroed by the conv kernel that precedes this launch.
// ---------------------------------------------------------------------------
__global__ void __launch_bounds__(256, 2) fused_kernel(
    const __half* __restrict__ f0h, const __half* __restrict__ f1h,
    const float* __restrict__ qw, const float* __restrict__ qb,
    const float* __restrict__ kw, const float* __restrict__ kb,
    __half* __restrict__ qh, __half* __restrict__ kh,
    float* __restrict__ flow_pred, float* __restrict__ flow)
{
    extern __shared__ char smem[];
    const int bid = blockIdx.x;

    if (bid < 192) {
        const int idx = bid, b = idx / 24;
        proj_body(f0h, qw, qb, kw, kb, qh, kh, b, (idx % 24) * 128, smem);
        __threadfence();
        __syncthreads();
        if (threadIdx.x == 0) atomicAdd(&g_done[b], 1);
    } else if (bid < 576) {
        const int idx = bid - 192, b = idx / 48;
        flash_body<0>(f0h, f1h, nullptr, flow_pred, b, (idx % 48) * 64, smem);
        __threadfence();
        __syncthreads();
        if (threadIdx.x == 0) atomicAdd(&g_done[b], 1);
    } else {
        const int idx = bid - 576, b = idx / 48;
        if (threadIdx.x == 0) {
            while (atomicAdd(&g_done[b], 0) < 72) __nanosleep(200);
            __threadfence();
        }
        __syncthreads();
        flash_body<1>(qh, kh, flow_pred, flow, b, (idx % 48) * 64, smem);
    }
}

// ---------------------------------------------------------------------------
// Fused transpose+convert (also re-zeroes g_done for the following launch):
// z<8 -> f0->f0h (x1), z>=8 -> f1->f1h (xS2)
// ---------------------------------------------------------------------------
__global__ void __launch_bounds__(256) convH2_kernel(
    const float* __restrict__ f0, const float* __restrict__ f1,
    __half* __restrict__ o0, __half* __restrict__ o1)
{
    __shared__ float tile[32][33];
    if (blockIdx.x == 0 && blockIdx.y == 0 && blockIdx.z == 0 &&
        threadIdx.x < BATCH && threadIdx.y == 0)
        g_done[threadIdx.x] = 0;

    const int z = blockIdx.z, b = z & 7;
    const float* in = (z < 8) ? f0 : f1;
    __half* out = (z < 8) ? o0 : o1;
    const float scale = (z < 8) ? 1.0f : S2F;
    const int n0 = blockIdx.x * 32, c0 = blockIdx.y * 32;
    const int tx = threadIdx.x, ty = threadIdx.y;

    const float* ip = in + ((size_t)b * CH + c0) * NN + n0;
    #pragma unroll
    for (int i = 0; i < 4; i++) {
        int c = ty + i * 8;
        tile[c][tx] = ip[(size_t)c * NN + tx];
    }
    __syncthreads();
    __half* op = out + ((size_t)b * NN + n0) * CH + c0;
    #pragma unroll
    for (int i = 0; i < 4; i++) {
        int nr = ty + i * 8;
        op[(size_t)nr * CH + tx] = __float2half(tile[tx][nr] * scale);
    }
}

extern "C" void kernel_launch(void* const* d_in, const int* in_sizes, int n_in,
                              void* d_out, int out_size)
{
    const float* f0 = (const float*)d_in[0];
    const float* f1 = (const float*)d_in[1];
    const float* qw = (const float*)d_in[2];
    const float* qb = (const float*)d_in[3];
    const float* kw = (const float*)d_in[4];
    const float* kb = (const float*)d_in[5];

    float* out       = (float*)d_out;
    float* flow      = out;
    float* flow_pred = out + (size_t)BATCH * 2 * NN;

    void* p;
    cudaGetSymbolAddress(&p, g_f0h); __half* f0h = (__half*)p;
    cudaGetSymbolAddress(&p, g_f1h); __half* f1h = (__half*)p;
    cudaGetSymbolAddress(&p, g_qh);  __half* qh  = (__half*)p;
    cudaGetSymbolAddress(&p, g_kh);  __half* kh  = (__half*)p;

    cudaFuncSetAttribute(fused_kernel, cudaFuncAttributeMaxDynamicSharedMemorySize, FSM_TOT);

    dim3 cgrid(NN / 32, CH / 32, 2 * BATCH);
    dim3 cblk(32, 8);

    convH2_kernel<<<cgrid, cblk>>>(f0, f1, f0h, f1h);
    fused_kernel<<<960, 256, FSM_TOT>>>(f0h, f1h, qw, qb, kw, kb, qh, kh,
                                        flow_pred, flow);
}

// round 10
// speedup vs baseline: 1.1816x; 1.0472x over previous
#include <cuda_runtime.h>
#include <cuda_fp16.h>
#include <cstdint>

#define BATCH 8
#define CH    128
#define HH    48
#define WW    64
#define NN    (HH*WW)   // 3072

#define S2F ((float)(1.4426950408889634 * 0.088388347648318447))

__device__ __half g_f0h[BATCH*NN*CH];
__device__ __half g_f1h[BATCH*NN*CH];
__device__ __half g_qh [BATCH*NN*CH];
__device__ __half g_kh [BATCH*NN*CH];
__device__ int    g_done[BATCH];       // stage0 completions per batch (target 72)

__device__ __forceinline__ uint32_t smem_u32(const void* p) {
    uint32_t a;
    asm("{ .reg .u64 t; cvta.to.shared.u64 t, %1; cvt.u32.u64 %0, t; }" : "=r"(a) : "l"(p));
    return a;
}
__device__ __forceinline__ void ldsm4(uint32_t* r, uint32_t addr) {
    asm volatile("ldmatrix.sync.aligned.m8n8.x4.shared.b16 {%0,%1,%2,%3}, [%4];"
        : "=r"(r[0]), "=r"(r[1]), "=r"(r[2]), "=r"(r[3]) : "r"(addr));
}
__device__ __forceinline__ void mma16816(float* c, const uint32_t* a, const uint32_t* b) {
    asm volatile("mma.sync.aligned.m16n8k16.row.col.f32.f16.f16.f32 "
        "{%0,%1,%2,%3}, {%4,%5,%6,%7}, {%8,%9}, {%0,%1,%2,%3};"
        : "+f"(c[0]), "+f"(c[1]), "+f"(c[2]), "+f"(c[3])
        : "r"(a[0]), "r"(a[1]), "r"(a[2]), "r"(a[3]), "r"(b[0]), "r"(b[1]));
}
__device__ __forceinline__ float ex2f(float x) {
    float y; asm("ex2.approx.f32 %0, %1;" : "=f"(y) : "f"(x)); return y;
}
#define CP16(dst, src) asm volatile("cp.async.cg.shared.global [%0], [%1], 16;" :: "r"(dst), "l"(src))
#define CP_COMMIT()    asm volatile("cp.async.commit_group;" ::: "memory")
#define CP_WAIT0()     asm volatile("cp.async.wait_group 0;" ::: "memory")
#define GBAR(id)       asm volatile("bar.sync %0, 128;" :: "r"(id) : "memory")

#define RS 136

// Flash smem: A tile (64q) + per-group double-buffered 64-key B half-tiles
#define FSM_A    0                    // 17408
#define FSM_B    17408                // 4 x 17408 (group g, buf c at (g*2+c))
#define FSM_V    87040                // 4 x 512
#define FSM_RED  89088                // 192 floats
#define FSM_TOT  90112

// Proj smem map (fits inside FSM_TOT)
#define PSM_F   0
#define PSM_W   34816
#define PSM_QB  69632
#define PSM_KB  70144

// 64-row half-tile prefetch by one 128-thread group (tl = t & 127)
__device__ __forceinline__ void prefetch_half(uint32_t dstBase, const __half* src, int tl) {
    #pragma unroll
    for (int it = 0; it < 8; it++) {
        int idx = it * 128 + tl;
        int r = idx >> 4, g = idx & 15;
        CP16(dstBase + (uint32_t)((r * RS + g * 8) * 2), src + (size_t)r * CH + g * 8);
    }
}

// ---------------------------------------------------------------------------
// Flash body: 64-query tile, 24 key tiles of 128 keys. The CTA is split into
// two INDEPENDENT 128-thread pipelines (wc = wid>>2): group wc owns key rows
// [wc*64, wc*64+64) of every tile, with its own double-buffered half-tile and
// its own named barrier — the groups drift/anti-phase so one group's MMA
// fills the other's ex2-epilogue bubbles. Cross-group softmax reduction at
// the end via block-wide __syncthreads (unchanged).
// ---------------------------------------------------------------------------
template<int MODE>
__device__ __forceinline__ void flash_body(
    const __half* __restrict__ A, const __half* __restrict__ Bm,
    const float* __restrict__ vsrc, float* __restrict__ out,
    int b, int n0, char* smem)
{
    const uint32_t sb = smem_u32(smem);
    const int t = threadIdx.x, wid = t >> 5, lane = t & 31;
    const int wc = wid >> 2, wr = wid & 3;   // group / row-block
    const int tl = t & 127;                  // lane within group
    const size_t vbase = (size_t)b * 2 * NN;

    {   // query tile: 64 rows (all 256 threads)
        __half* sA = (__half*)smem;
        const __half* src = A + ((size_t)b * NN + n0) * CH;
        #pragma unroll
        for (int it = 0; it < 4; it++) {
            int idx = it * 256 + t;
            int r = idx >> 4, g = idx & 15;
            *(uint4*)(sA + r * RS + g * 8) = *(const uint4*)(src + (size_t)r * CH + g * 8);
        }
    }

    // Group g's source rows for tile T start at T*128 + wc*64
    const __half* Bg = Bm + ((size_t)b * NN + wc * 64) * CH;
    const uint32_t bBuf0 = sb + FSM_B + (uint32_t)(wc * 2) * 17408;
    const uint32_t bBuf1 = bBuf0 + 17408;
    const uint32_t vBuf0 = sb + FSM_V + (uint32_t)(wc * 2) * 512;
    const uint32_t vBuf1 = vBuf0 + 512;

    prefetch_half(bBuf0, Bg, tl);
    if (MODE == 1 && tl < 32) {
        const float* s = (tl < 16) ? (vsrc + vbase + wc * 64 + tl * 4)
                                   : (vsrc + vbase + NN + wc * 64 + (tl - 16) * 4);
        CP16(vBuf0 + ((tl < 16) ? tl * 16 : 256 + (tl - 16) * 16), s);
    }
    CP_COMMIT();

    const int g8 = (lane >> 3) & 1, g16 = lane >> 4, l7 = lane & 7, tid4 = lane & 3;
    const uint32_t aBase = sb + FSM_A + (uint32_t)(((wr * 16 + l7 + g8 * 8) * RS + g16 * 8) * 2);
    const uint32_t bOff  = (uint32_t)(((l7 + g16 * 8) * RS + g8 * 8) * 2);

    // Tile-0 halves + sA ready (block-wide once); hoist A fragments
    CP_WAIT0();
    __syncthreads();
    uint32_t aF[8][4];
    #pragma unroll
    for (int k = 0; k < 8; k++) ldsm4(aF[k], aBase + k * 32);

    // Prefetch tile 1 into buf1 (per group)
    prefetch_half(bBuf1, Bg + (size_t)128 * CH, tl);
    if (MODE == 1 && tl < 32) {
        const float* s = (tl < 16) ? (vsrc + vbase + 128 + wc * 64 + tl * 4)
                                   : (vsrc + vbase + NN + 128 + wc * 64 + (tl - 16) * 4);
        CP16(vBuf1 + ((tl < 16) ? tl * 16 : 256 + (tl - 16) * 16), s);
    }
    CP_COMMIT();

    float L[2] = {0.f, 0.f}, AX[2] = {0.f, 0.f}, AY[2] = {0.f, 0.f};

    for (int tile = 0; tile < NN / 128; tile++) {
        const uint32_t cur = tile & 1;
        if (tile > 0) {
            CP_WAIT0();                    // this tile's half ready
            GBAR(1 + wc);                  // group done reading buf being refilled
            if (tile + 1 < NN / 128) {
                const int mn = (tile + 1) * 128;
                prefetch_half(cur ? bBuf0 : bBuf1, Bg + (size_t)mn * CH, tl);
                if (MODE == 1 && tl < 32) {
                    const float* s = (tl < 16)
                        ? (vsrc + vbase + mn + wc * 64 + tl * 4)
                        : (vsrc + vbase + NN + mn + wc * 64 + (tl - 16) * 4);
                    CP16((cur ? vBuf0 : vBuf1)
                         + ((tl < 16) ? tl * 16 : 256 + (tl - 16) * 16), s);
                }
                CP_COMMIT();
            }
        }

        const uint32_t bB = (cur ? bBuf1 : bBuf0) + bOff;
        const float* sV = (const float*)(smem + ((cur ? vBuf1 : vBuf0) - sb));

        float c[8][4];
        #pragma unroll
        for (int j = 0; j < 8; j++)
            #pragma unroll
            for (int q = 0; q < 4; q++) c[j][q] = 0.f;

        #pragma unroll
        for (int k = 0; k < 8; k++) {
            #pragma unroll
            for (int j2 = 0; j2 < 4; j2++) {
                uint32_t bb[4];
                ldsm4(bb, bB + j2 * (16 * RS * 2) + k * 32);
                mma16816(c[2 * j2],     aF[k], bb);
                mma16816(c[2 * j2 + 1], aF[k], bb + 2);
            }
        }

        float Lt0 = 0.f, Lt1 = 0.f;
        #pragma unroll
        for (int j = 0; j < 8; j++) {
            float p0 = ex2f(c[j][0]);
            float p1 = ex2f(c[j][1]);
            float p2 = ex2f(c[j][2]);
            float p3 = ex2f(c[j][3]);
            if (MODE == 0) {
                float vx0 = (float)(j * 8 + tid4 * 2);   // m & 63 (wc adds bit 6)
                float vx1 = vx0 + 1.f;
                Lt0 += p0 + p1;  Lt1 += p2 + p3;
                AX[0] += p0 * vx0 + p1 * vx1;
                AX[1] += p2 * vx0 + p3 * vx1;
            } else {
                int cl = j * 8 + tid4 * 2;               // local within half
                float2 x2 = *(const float2*)&sV[cl];
                float2 y2 = *(const float2*)&sV[64 + cl];
                L[0]  += p0 + p1;          L[1]  += p2 + p3;
                AX[0] += p0 * x2.x + p1 * x2.y;
                AX[1] += p2 * x2.x + p3 * x2.y;
                AY[0] += p0 * y2.x + p1 * y2.y;
                AY[1] += p2 * y2.x + p3 * y2.y;
            }
        }
        if (MODE == 0) {
            float vy = (float)(2 * tile + wc);           // m >> 6
            L[0] += Lt0;  L[1] += Lt1;
            AY[0] += vy * Lt0;  AY[1] += vy * Lt1;
        }
    }

    #pragma unroll
    for (int o = 1; o <= 2; o <<= 1)
        #pragma unroll
        for (int h = 0; h < 2; h++) {
            L[h]  += __shfl_xor_sync(0xffffffffu, L[h],  o);
            AX[h] += __shfl_xor_sync(0xffffffffu, AX[h], o);
            AY[h] += __shfl_xor_sync(0xffffffffu, AY[h], o);
        }

    // Cross-group reduction (block-wide syncs: both groups have left the loop)
    float* red = (float*)(smem + FSM_RED);
    __syncthreads();
    if (wc == 1 && tid4 == 0) {
        #pragma unroll
        for (int h = 0; h < 2; h++) {
            int rl = wr * 16 + h * 8 + (lane >> 2);
            red[rl]       = L[h];
            red[64 + rl]  = AX[h];
            red[128 + rl] = AY[h];
        }
    }
    __syncthreads();
    if (wc == 0 && tid4 == 0) {
        float* ob = out + vbase;
        #pragma unroll
        for (int h = 0; h < 2; h++) {
            int rl = wr * 16 + h * 8 + (lane >> 2);
            float Lt  = L[h]  + red[rl];
            float AXt = AX[h] + red[64 + rl];
            float AYt = AY[h] + red[128 + rl];
            int n = n0 + rl;
            float fx = AXt / Lt, fy = AYt / Lt;
            if (MODE == 0) { fx -= (float)(n & (WW - 1)); fy -= (float)(n >> 6); }
            ob[n] = fx;  ob[NN + n] = fy;
        }
    }
}

// ---------------------------------------------------------------------------
// Proj body (unchanged R8): 128-row tile; q kept in regs as GEMM2 A-fragments.
// ---------------------------------------------------------------------------
__device__ __forceinline__ void proj_body(
    const __half* __restrict__ F0, const float* __restrict__ qw,
    const float* __restrict__ qb,  const float* __restrict__ kw,
    const float* __restrict__ kb,
    __half* __restrict__ QH, __half* __restrict__ KH,
    int b, int n0, char* smem)
{
    __half* sF = (__half*)(smem + PSM_F);
    __half* sW = (__half*)(smem + PSM_W);
    float* qbS = (float*)(smem + PSM_QB);
    float* kbS = (float*)(smem + PSM_KB);
    const uint32_t sbF = smem_u32(sF), sbW = smem_u32(sW);

    const int t = threadIdx.x, wid = t >> 5, lane = t & 31;

    {
        const __half* src = F0 + ((size_t)b * NN + n0) * CH;
        #pragma unroll
        for (int it = 0; it < 8; it++) {
            int idx = it * 256 + t;
            int r = idx >> 4, g = idx & 15;
            *(uint4*)(sF + r * RS + g * 8) = *(const uint4*)(src + (size_t)r * CH + g * 8);
        }
    }
    #pragma unroll
    for (int it = 0; it < 16; it++) {
        int idx = it * 256 + t;
        int r = idx >> 5, g = idx & 31;
        float4 w = *(const float4*)(qw + (size_t)r * CH + g * 4);
        __half h[4] = {__float2half(w.x), __float2half(w.y), __float2half(w.z), __float2half(w.w)};
        *(uint2*)(sW + r * RS + g * 4) = *(uint2*)h;
    }
    if (t < 128) { qbS[t] = qb[t]; kbS[t] = kb[t]; }
    __syncthreads();

    const int g8 = (lane >> 3) & 1, g16 = lane >> 4, l7 = lane & 7, tid4 = lane & 3;
    const uint32_t aBase = sbF + (uint32_t)(((wid * 16 + l7 + g8 * 8) * RS + g16 * 8) * 2);
    const uint32_t bBase = sbW + (uint32_t)(((l7 + g16 * 8) * RS + g8 * 8) * 2);

    float c[16][4];
    #pragma unroll
    for (int j = 0; j < 16; j++)
        #pragma unroll
        for (int q = 0; q < 4; q++) c[j][q] = 0.f;
    #pragma unroll
    for (int k = 0; k < 8; k++) {
        uint32_t a[4];
        ldsm4(a, aBase + k * 32);
        #pragma unroll
        for (int j2 = 0; j2 < 8; j2++) {
            uint32_t bb[4];
            ldsm4(bb, bBase + j2 * (16 * RS * 2) + k * 32);
            mma16816(c[2 * j2],     a, bb);
            mma16816(c[2 * j2 + 1], a, bb + 2);
        }
    }

    uint32_t hq[16][2];
    const int r0 = wid * 16 + (lane >> 2);
    #pragma unroll
    for (int j = 0; j < 16; j++) {
        int col = j * 8 + tid4 * 2;
        float b0 = qbS[col], b1 = qbS[col + 1];
        __half2 v0 = __floats2half2_rn(c[j][0] + b0, c[j][1] + b1);
        __half2 v1 = __floats2half2_rn(c[j][2] + b0, c[j][3] + b1);
        hq[j][0] = *(uint32_t*)&v0;
        hq[j][1] = *(uint32_t*)&v1;
        *(uint32_t*)(QH + ((size_t)b * NN + n0 + r0) * CH + col)     = hq[j][0];
        *(uint32_t*)(QH + ((size_t)b * NN + n0 + r0 + 8) * CH + col) = hq[j][1];
    }

    __syncthreads();
    #pragma unroll
    for (int it = 0; it < 16; it++) {
        int idx = it * 256 + t;
        int r = idx >> 5, g = idx & 31;
        float4 w = *(const float4*)(kw + (size_t)r * CH + g * 4);
        __half h[4] = {__float2half(w.x), __float2half(w.y), __float2half(w.z), __float2half(w.w)};
        *(uint2*)(sW + r * RS + g * 4) = *(uint2*)h;
    }
    __syncthreads();

    float c2[16][4];
    #pragma unroll
    for (int j = 0; j < 16; j++)
        #pragma unroll
        for (int q = 0; q < 4; q++) c2[j][q] = 0.f;
    #pragma unroll
    for (int kk = 0; kk < 8; kk++) {
        uint32_t a[4] = { hq[2 * kk][0], hq[2 * kk][1], hq[2 * kk + 1][0], hq[2 * kk + 1][1] };
        #pragma unroll
        for (int j2 = 0; j2 < 8; j2++) {
            uint32_t bb[4];
            ldsm4(bb, bBase + j2 * (16 * RS * 2) + kk * 32);
            mma16816(c2[2 * j2],     a, bb);
            mma16816(c2[2 * j2 + 1], a, bb + 2);
        }
    }
    #pragma unroll
    for (int j = 0; j < 16; j++) {
        int col = j * 8 + tid4 * 2;
        float b0 = kbS[col], b1 = kbS[col + 1];
        __half2 v0 = __floats2half2_rn((c2[j][0] + b0) * S2F, (c2[j][1] + b1) * S2F);
        __half2 v1 = __floats2half2_rn((c2[j][2] + b0) * S2F, (c2[j][3] + b1) * S2F);
        *(uint32_t*)(KH + ((size_t)b * NN + n0 + r0) * CH + col)     = *(uint32_t*)&v0;
        *(uint32_t*)(KH + ((size_t)b * NN + n0 + r0 + 8) * CH + col) = *(uint32_t*)&v1;
    }
}

// ---------------------------------------------------------------------------
// Fused pipeline kernel (R9 structure): proj -> flash0 -> flash1 in bid order,
// flash1 gated per batch on g_done[b] == 72.
// ---------------------------------------------------------------------------
__global__ void __launch_bounds__(256, 2) fused_kernel(
    const __half* __restrict__ f0h, const __half* __restrict__ f1h,
    const float* __restrict__ qw, const float* __restrict__ qb,
    const float* __restrict__ kw, const float* __restrict__ kb,
    __half* __restrict__ qh, __half* __restrict__ kh,
    float* __restrict__ flow_pred, float* __restrict__ flow)
{
    extern __shared__ char smem[];
    const int bid = blockIdx.x;

    if (bid < 192) {
        const int idx = bid, b = idx / 24;
        proj_body(f0h, qw, qb, kw, kb, qh, kh, b, (idx % 24) * 128, smem);
        __threadfence();
        __syncthreads();
        if (threadIdx.x == 0) atomicAdd(&g_done[b], 1);
    } else if (bid < 576) {
        const int idx = bid - 192, b = idx / 48;
        flash_body<0>(f0h, f1h, nullptr, flow_pred, b, (idx % 48) * 64, smem);
        __threadfence();
        __syncthreads();
        if (threadIdx.x == 0) atomicAdd(&g_done[b], 1);
    } else {
        const int idx = bid - 576, b = idx / 48;
        if (threadIdx.x == 0) {
            while (atomicAdd(&g_done[b], 0) < 72) __nanosleep(200);
            __threadfence();
        }
        __syncthreads();
        flash_body<1>(qh, kh, flow_pred, flow, b, (idx % 48) * 64, smem);
    }
}

// ---------------------------------------------------------------------------
// Fused transpose+convert (re-zeroes g_done): z<8 f0->f0h (x1), z>=8 f1 (xS2)
// ---------------------------------------------------------------------------
__global__ void __launch_bounds__(256) convH2_kernel(
    const float* __restrict__ f0, const float* __restrict__ f1,
    __half* __restrict__ o0, __half* __restrict__ o1)
{
    __shared__ float tile[32][33];
    if (blockIdx.x == 0 && blockIdx.y == 0 && blockIdx.z == 0 &&
        threadIdx.x < BATCH && threadIdx.y == 0)
        g_done[threadIdx.x] = 0;

    const int z = blockIdx.z, b = z & 7;
    const float* in = (z < 8) ? f0 : f1;
    __half* out = (z < 8) ? o0 : o1;
    const float scale = (z < 8) ? 1.0f : S2F;
    const int n0 = blockIdx.x * 32, c0 = blockIdx.y * 32;
    const int tx = threadIdx.x, ty = threadIdx.y;

    const float* ip = in + ((size_t)b * CH + c0) * NN + n0;
    #pragma unroll
    for (int i = 0; i < 4; i++) {
        int c = ty + i * 8;
        tile[c][tx] = ip[(size_t)c * NN + tx];
    }
    __syncthreads();
    __half* op = out + ((size_t)b * NN + n0) * CH + c0;
    #pragma unroll
    for (int i = 0; i < 4; i++) {
        int nr = ty + i * 8;
        op[(size_t)nr * CH + tx] = __float2half(tile[tx][nr] * scale);
    }
}

extern "C" void kernel_launch(void* const* d_in, const int* in_sizes, int n_in,
                              void* d_out, int out_size)
{
    const float* f0 = (const float*)d_in[0];
    const float* f1 = (const float*)d_in[1];
    const float* qw = (const float*)d_in[2];
    const float* qb = (const float*)d_in[3];
    const float* kw = (const float*)d_in[4];
    const float* kb = (const float*)d_in[5];

    float* out       = (float*)d_out;
    float* flow      = out;
    float* flow_pred = out + (size_t)BATCH * 2 * NN;

    void* p;
    cudaGetSymbolAddress(&p, g_f0h); __half* f0h = (__half*)p;
    cudaGetSymbolAddress(&p, g_f1h); __half* f1h = (__half*)p;
    cudaGetSymbolAddress(&p, g_qh);  __half* qh  = (__half*)p;
    cudaGetSymbolAddress(&p, g_kh);  __half* kh  = (__half*)p;

    cudaFuncSetAttribute(fused_kernel, cudaFuncAttributeMaxDynamicSharedMemorySize, FSM_TOT);

    dim3 cgrid(NN / 32, CH / 32, 2 * BATCH);
    dim3 cblk(32, 8);

    convH2_kernel<<<cgrid, cblk>>>(f0, f1, f0h, f1h);
    fused_kernel<<<960, 256, FSM_TOT>>>(f0h, f1h, qw, qb, kw, kb, qh, kh,
                                        flow_pred, flow);
}